// round 2
// baseline (speedup 1.0000x reference)
#include <cuda_runtime.h>
#include <math.h>

#define BATCH 64
#define DIM 1024

// Scratch (static device arrays — no allocation at launch time)
__device__ float g_tmp[67108864];     // 64 x 1024 x 1024 fp32: tmp = sigma_in @ w_mu (256 MB)
__device__ float g_wsigT[1048576];    // wsigT[k][i] = softplus(w_sigma[i][k])
__device__ float g_dvec[65536];       // dvec[b][k] = sigma_in[b][k][k] + mu_in[b][k]^2
__device__ float g_diag[65536];       // diag_term[b][i]

// ---------------------------------------------------------------------------
// Prep: transposed softplus of w_sigma.  wsigT[k][i] = log1p(exp(w_sigma[i*N+k]))
// ---------------------------------------------------------------------------
__global__ void prep_wsig_kernel(const float* __restrict__ w_sigma) {
    int k = blockIdx.x;
    for (int i = threadIdx.x; i < DIM; i += blockDim.x) {
        float x = w_sigma[i * DIM + k];
        g_wsigT[k * DIM + i] = log1pf(expf(x));
    }
}

// ---------------------------------------------------------------------------
// Prep: dvec[b][k] = sigma_in[b][k][k] + mu_in[b][k]^2
// ---------------------------------------------------------------------------
__global__ void prep_dvec_kernel(const float* __restrict__ sigma_in,
                                 const float* __restrict__ mu_in) {
    int idx = blockIdx.x * blockDim.x + threadIdx.x;  // b*DIM + k
    if (idx < BATCH * DIM) {
        int b = idx >> 10;
        int k = idx & 1023;
        float m = mu_in[idx];
        g_dvec[idx] = sigma_in[(size_t)b * DIM * DIM + (size_t)k * DIM + k] + m * m;
    }
}

// ---------------------------------------------------------------------------
// mu_out[b][o] = sum_i w_mu[i][o] * mu_in[b][i] + b_mu[o]
// ---------------------------------------------------------------------------
__global__ void mu_out_kernel(const float* __restrict__ mu_in,
                              const float* __restrict__ w_mu,
                              const float* __restrict__ b_mu,
                              float* __restrict__ out) {
    int b = blockIdx.x;
    int o = blockIdx.y * 256 + threadIdx.x;
    const float* mi = mu_in + b * DIM;
    float acc = 0.f;
#pragma unroll 8
    for (int i = 0; i < DIM; i++) {
        acc += mi[i] * w_mu[i * DIM + o];   // coalesced across threads
    }
    out[b * DIM + o] = acc + b_mu[o];
}

// ---------------------------------------------------------------------------
// diag_term[b][i] = sum_k dvec[b][k] * wsigT[k][i] + softplus(b_sigma[i])
// ---------------------------------------------------------------------------
__global__ void diag_kernel(const float* __restrict__ b_sigma) {
    int b = blockIdx.x;
    int i = blockIdx.y * 256 + threadIdx.x;
    const float* dv = g_dvec + b * DIM;
    float acc = 0.f;
#pragma unroll 8
    for (int k = 0; k < DIM; k++) {
        acc += dv[k] * g_wsigT[k * DIM + i];  // coalesced across threads
    }
    g_diag[b * DIM + i] = acc + log1pf(expf(b_sigma[i]));
}

// ---------------------------------------------------------------------------
// KL: 0.5 * sum_i ( ||w_mu[:,i]||^2 + sum_k wsig[i][k] - DIM - logdet_i )
// det_i = prod_k wsig[i][k]  (underflows to 0 -> logdet = -1000, matching ref)
// ---------------------------------------------------------------------------
__global__ void kl_kernel(const float* __restrict__ w_mu, float* __restrict__ out_kl) {
    int i = threadIdx.x;  // 1024 threads, 1 block
    float sq = 0.f, tr = 0.f, det = 1.0f;
    for (int k = 0; k < DIM; k++) {
        float w = w_mu[k * DIM + i];
        sq += w * w;
        float s = g_wsigT[k * DIM + i];
        tr += s;
        det *= s;
    }
    float logdet = (det > 0.f) ? logf(det) : -1000.0f;
    float v = sq + tr - (float)DIM - logdet;
    __shared__ float red[1024];
    red[i] = v;
    __syncthreads();
    for (int s = 512; s > 0; s >>= 1) {
        if (i < s) red[i] += red[i + s];
        __syncthreads();
    }
    if (i == 0) *out_kl = 0.5f * red[0];
}

// ---------------------------------------------------------------------------
// SGEMM tiles: 128x128 block, 8x8 per thread, BK=8, 256 threads
// ---------------------------------------------------------------------------
#define BM 128
#define BN 128
#define BK 8
#define TM 8
#define TN 8

// GEMM1: tmp[b][k][j] = sum_l sigma_in[b][k][l] * w_mu[l][j]
__global__ __launch_bounds__(256, 2) void gemm1_kernel(const float* __restrict__ Sg,
                                                       const float* __restrict__ W) {
    int b = blockIdx.z;
    const float* A = Sg + (size_t)b * DIM * DIM;   // [M=k][K=l], row-major
    float* C = g_tmp + (size_t)b * DIM * DIM;

    __shared__ float As[BK][BM];
    __shared__ float Bs[BK][BN];

    int tid = threadIdx.x;
    int ty = tid >> 4;        // 0..15 -> rows ty*8..ty*8+7
    int tx = tid & 15;        // 0..15 -> cols tx*8..tx*8+7
    int rowBase = blockIdx.y * BM;
    int colBase = blockIdx.x * BN;

    float acc[TM][TN];
#pragma unroll
    for (int m = 0; m < TM; m++)
#pragma unroll
        for (int n = 0; n < TN; n++) acc[m][n] = 0.f;

    int aRow = tid >> 1, aCol = (tid & 1) * 4;          // A: 128 rows x 8 cols
    int bRow = tid >> 5, bCol = (tid & 31) * 4;         // B: 8 rows x 128 cols
    const float* Aptr = A + (size_t)(rowBase + aRow) * DIM + aCol;
    const float* Bptr = W + (size_t)bRow * DIM + colBase + bCol;

    for (int l0 = 0; l0 < DIM; l0 += BK) {
        float4 av = *(const float4*)(Aptr + l0);
        As[aCol + 0][aRow] = av.x;
        As[aCol + 1][aRow] = av.y;
        As[aCol + 2][aRow] = av.z;
        As[aCol + 3][aRow] = av.w;
        *(float4*)&Bs[bRow][bCol] = *(const float4*)(Bptr + (size_t)l0 * DIM);
        __syncthreads();
#pragma unroll
        for (int kk = 0; kk < BK; kk++) {
            float ar[TM], br[TN];
#pragma unroll
            for (int m = 0; m < TM; m++) ar[m] = As[kk][ty * TM + m];
#pragma unroll
            for (int n = 0; n < TN; n++) br[n] = Bs[kk][tx * TN + n];
#pragma unroll
            for (int m = 0; m < TM; m++)
#pragma unroll
                for (int n = 0; n < TN; n++) acc[m][n] += ar[m] * br[n];
        }
        __syncthreads();
    }

#pragma unroll
    for (int m = 0; m < TM; m++) {
        int r = rowBase + ty * TM + m;
        float* cp = C + (size_t)r * DIM + colBase + tx * TN;
        *(float4*)cp = make_float4(acc[m][0], acc[m][1], acc[m][2], acc[m][3]);
        *(float4*)(cp + 4) = make_float4(acc[m][4], acc[m][5], acc[m][6], acc[m][7]);
    }
}

// GEMM2: Sigma[b][i][j] = sum_k w_mu[k][i] * tmp[b][k][j]  (+ diag_term on i==j)
__global__ __launch_bounds__(256, 2) void gemm2_kernel(const float* __restrict__ W,
                                                       float* __restrict__ out_sigma) {
    int b = blockIdx.z;
    const float* Btmp = g_tmp + (size_t)b * DIM * DIM;   // [K=k][N=j]
    float* C = out_sigma + (size_t)b * DIM * DIM;

    __shared__ float As[BK][BM];   // As[k][i] from w_mu[k][i] (already K-outer)
    __shared__ float Bs[BK][BN];

    int tid = threadIdx.x;
    int ty = tid >> 4;
    int tx = tid & 15;
    int rowBase = blockIdx.y * BM;   // i
    int colBase = blockIdx.x * BN;   // j

    float acc[TM][TN];
#pragma unroll
    for (int m = 0; m < TM; m++)
#pragma unroll
        for (int n = 0; n < TN; n++) acc[m][n] = 0.f;

    int aRow = tid >> 5, aCol = (tid & 31) * 4;   // A: 8 rows(k) x 128 cols(i)
    int bRow = tid >> 5, bCol = (tid & 31) * 4;   // B: 8 rows(k) x 128 cols(j)
    const float* Aptr = W + (size_t)aRow * DIM + rowBase + aCol;
    const float* Bptr = Btmp + (size_t)bRow * DIM + colBase + bCol;

    for (int k0 = 0; k0 < DIM; k0 += BK) {
        *(float4*)&As[aRow][aCol] = *(const float4*)(Aptr + (size_t)k0 * DIM);
        *(float4*)&Bs[bRow][bCol] = *(const float4*)(Bptr + (size_t)k0 * DIM);
        __syncthreads();
#pragma unroll
        for (int kk = 0; kk < BK; kk++) {
            float ar[TM], br[TN];
#pragma unroll
            for (int m = 0; m < TM; m++) ar[m] = As[kk][ty * TM + m];
#pragma unroll
            for (int n = 0; n < TN; n++) br[n] = Bs[kk][tx * TN + n];
#pragma unroll
            for (int m = 0; m < TM; m++)
#pragma unroll
                for (int n = 0; n < TN; n++) acc[m][n] += ar[m] * br[n];
        }
        __syncthreads();
    }

#pragma unroll
    for (int m = 0; m < TM; m++) {
        int r = rowBase + ty * TM + m;   // global i
        int c0 = colBase + tx * TN;      // global j start
        // fuse diagonal add
        if (r >= c0 && r < c0 + TN) {
            acc[m][r - c0] += g_diag[b * DIM + r];
        }
        float* cp = C + (size_t)r * DIM + c0;
        *(float4*)cp = make_float4(acc[m][0], acc[m][1], acc[m][2], acc[m][3]);
        *(float4*)(cp + 4) = make_float4(acc[m][4], acc[m][5], acc[m][6], acc[m][7]);
    }
}

// ---------------------------------------------------------------------------
// Launch
// Output layout assumed: [ mu_out (64*1024) | Sigma_out (64*1024*1024) | kl (1) ]
// ---------------------------------------------------------------------------
extern "C" void kernel_launch(void* const* d_in, const int* in_sizes, int n_in,
                              void* d_out, int out_size) {
    const float* mu_in    = (const float*)d_in[0];
    const float* sigma_in = (const float*)d_in[1];
    const float* w_mu     = (const float*)d_in[2];
    const float* w_sigma  = (const float*)d_in[3];
    const float* b_mu     = (const float*)d_in[4];
    const float* b_sigma  = (const float*)d_in[5];
    float* out = (float*)d_out;

    float* out_mu    = out;                                   // 65536
    float* out_sigma = out + (size_t)BATCH * DIM;             // 64*1024*1024
    float* out_kl    = out + (size_t)BATCH * DIM + (size_t)BATCH * DIM * DIM;  // 1

    prep_wsig_kernel<<<DIM, 256>>>(w_sigma);
    prep_dvec_kernel<<<(BATCH * DIM) / 256, 256>>>(sigma_in, mu_in);
    mu_out_kernel<<<dim3(BATCH, DIM / 256), 256>>>(mu_in, w_mu, b_mu, out_mu);
    diag_kernel<<<dim3(BATCH, DIM / 256), 256>>>(b_sigma);
    kl_kernel<<<1, 1024>>>(w_mu, out_kl);
    gemm1_kernel<<<dim3(DIM / BN, DIM / BM, BATCH), 256>>>(sigma_in, w_mu);
    gemm2_kernel<<<dim3(DIM / BN, DIM / BM, BATCH), 256>>>(w_mu, out_sigma);
}

// round 4
// speedup vs baseline: 1.0012x; 1.0012x over previous
#include <cuda_runtime.h>
#include <math.h>

#define BATCH 64
#define DIM 1024

// Scratch (static device arrays — no allocation at launch time)
__device__ float g_tmp[67108864];     // 64 x 1024 x 1024 fp32: tmp = sigma_in @ w_mu (256 MB)
__device__ float g_wsigT[1048576];    // wsigT[k][i] = softplus(w_sigma[i][k])
__device__ float g_dvec[65536];       // dvec[b][k] = sigma_in[b][k][k] + mu_in[b][k]^2
__device__ float g_diag[65536];       // diag_term[b][i]

// ---------------------------------------------------------------------------
// Prep: transposed softplus of w_sigma.  wsigT[k][i] = log1p(exp(w_sigma[i*N+k]))
// ---------------------------------------------------------------------------
__global__ void prep_wsig_kernel(const float* __restrict__ w_sigma) {
    int k = blockIdx.x;
    for (int i = threadIdx.x; i < DIM; i += blockDim.x) {
        float x = w_sigma[i * DIM + k];
        g_wsigT[k * DIM + i] = log1pf(expf(x));
    }
}

// ---------------------------------------------------------------------------
// Prep: dvec[b][k] = sigma_in[b][k][k] + mu_in[b][k]^2
// ---------------------------------------------------------------------------
__global__ void prep_dvec_kernel(const float* __restrict__ sigma_in,
                                 const float* __restrict__ mu_in) {
    int idx = blockIdx.x * blockDim.x + threadIdx.x;  // b*DIM + k
    if (idx < BATCH * DIM) {
        int b = idx >> 10;
        int k = idx & 1023;
        float m = mu_in[idx];
        g_dvec[idx] = sigma_in[(size_t)b * DIM * DIM + (size_t)k * DIM + k] + m * m;
    }
}

// ---------------------------------------------------------------------------
// mu_out[b][o] = sum_i w_mu[i][o] * mu_in[b][i] + b_mu[o]
// ---------------------------------------------------------------------------
__global__ void mu_out_kernel(const float* __restrict__ mu_in,
                              const float* __restrict__ w_mu,
                              const float* __restrict__ b_mu,
                              float* __restrict__ out) {
    int b = blockIdx.x;
    int o = blockIdx.y * 256 + threadIdx.x;
    const float* mi = mu_in + b * DIM;
    float acc = 0.f;
#pragma unroll 8
    for (int i = 0; i < DIM; i++) {
        acc += mi[i] * w_mu[i * DIM + o];   // coalesced across threads
    }
    out[b * DIM + o] = acc + b_mu[o];
}

// ---------------------------------------------------------------------------
// diag_term[b][i] = sum_k dvec[b][k] * wsigT[k][i] + softplus(b_sigma[i])
// ---------------------------------------------------------------------------
__global__ void diag_kernel(const float* __restrict__ b_sigma) {
    int b = blockIdx.x;
    int i = blockIdx.y * 256 + threadIdx.x;
    const float* dv = g_dvec + b * DIM;
    float acc = 0.f;
#pragma unroll 8
    for (int k = 0; k < DIM; k++) {
        acc += dv[k] * g_wsigT[k * DIM + i];  // coalesced across threads
    }
    g_diag[b * DIM + i] = acc + log1pf(expf(b_sigma[i]));
}

// ---------------------------------------------------------------------------
// KL: 0.5 * sum_i ( ||w_mu[:,i]||^2 + sum_k wsig[i][k] - DIM - logdet_i )
// det_i = prod_k wsig[i][k]  (underflows to 0 -> logdet = -1000, matching ref)
// ---------------------------------------------------------------------------
__global__ void kl_kernel(const float* __restrict__ w_mu, float* __restrict__ out_kl) {
    int i = threadIdx.x;  // 1024 threads, 1 block
    float sq = 0.f, tr = 0.f, det = 1.0f;
    for (int k = 0; k < DIM; k++) {
        float w = w_mu[k * DIM + i];
        sq += w * w;
        float s = g_wsigT[k * DIM + i];
        tr += s;
        det *= s;
    }
    float logdet = (det > 0.f) ? logf(det) : -1000.0f;
    float v = sq + tr - (float)DIM - logdet;
    __shared__ float red[1024];
    red[i] = v;
    __syncthreads();
    for (int s = 512; s > 0; s >>= 1) {
        if (i < s) red[i] += red[i + s];
        __syncthreads();
    }
    if (i == 0) *out_kl = 0.5f * red[0];
}

// ---------------------------------------------------------------------------
// SGEMM tiles: 128x128 block, 8x8 per thread, BK=8, 256 threads
// ---------------------------------------------------------------------------
#define BM 128
#define BN 128
#define BK 8
#define TM 8
#define TN 8

// GEMM1: tmp[b][k][j] = sum_l sigma_in[b][k][l] * w_mu[l][j]
__global__ __launch_bounds__(256, 2) void gemm1_kernel(const float* __restrict__ Sg,
                                                       const float* __restrict__ W) {
    int b = blockIdx.z;
    const float* A = Sg + (size_t)b * DIM * DIM;   // [M=k][K=l], row-major
    float* C = g_tmp + (size_t)b * DIM * DIM;

    __shared__ float As[BK][BM];
    __shared__ float Bs[BK][BN];

    int tid = threadIdx.x;
    int ty = tid >> 4;        // 0..15 -> rows ty*8..ty*8+7
    int tx = tid & 15;        // 0..15 -> cols tx*8..tx*8+7
    int rowBase = blockIdx.y * BM;
    int colBase = blockIdx.x * BN;

    float acc[TM][TN];
#pragma unroll
    for (int m = 0; m < TM; m++)
#pragma unroll
        for (int n = 0; n < TN; n++) acc[m][n] = 0.f;

    int aRow = tid >> 1, aCol = (tid & 1) * 4;          // A: 128 rows x 8 cols
    int bRow = tid >> 5, bCol = (tid & 31) * 4;         // B: 8 rows x 128 cols
    const float* Aptr = A + (size_t)(rowBase + aRow) * DIM + aCol;
    const float* Bptr = W + (size_t)bRow * DIM + colBase + bCol;

    for (int l0 = 0; l0 < DIM; l0 += BK) {
        float4 av = *(const float4*)(Aptr + l0);
        As[aCol + 0][aRow] = av.x;
        As[aCol + 1][aRow] = av.y;
        As[aCol + 2][aRow] = av.z;
        As[aCol + 3][aRow] = av.w;
        *(float4*)&Bs[bRow][bCol] = *(const float4*)(Bptr + (size_t)l0 * DIM);
        __syncthreads();
#pragma unroll
        for (int kk = 0; kk < BK; kk++) {
            float ar[TM], br[TN];
#pragma unroll
            for (int m = 0; m < TM; m++) ar[m] = As[kk][ty * TM + m];
#pragma unroll
            for (int n = 0; n < TN; n++) br[n] = Bs[kk][tx * TN + n];
#pragma unroll
            for (int m = 0; m < TM; m++)
#pragma unroll
                for (int n = 0; n < TN; n++) acc[m][n] += ar[m] * br[n];
        }
        __syncthreads();
    }

#pragma unroll
    for (int m = 0; m < TM; m++) {
        int r = rowBase + ty * TM + m;
        float* cp = C + (size_t)r * DIM + colBase + tx * TN;
        *(float4*)cp = make_float4(acc[m][0], acc[m][1], acc[m][2], acc[m][3]);
        *(float4*)(cp + 4) = make_float4(acc[m][4], acc[m][5], acc[m][6], acc[m][7]);
    }
}

// GEMM2: Sigma[b][i][j] = sum_k w_mu[k][i] * tmp[b][k][j]  (+ diag_term on i==j)
__global__ __launch_bounds__(256, 2) void gemm2_kernel(const float* __restrict__ W,
                                                       float* __restrict__ out_sigma) {
    int b = blockIdx.z;
    const float* Btmp = g_tmp + (size_t)b * DIM * DIM;   // [K=k][N=j]
    float* C = out_sigma + (size_t)b * DIM * DIM;

    __shared__ float As[BK][BM];   // As[k][i] from w_mu[k][i] (already K-outer)
    __shared__ float Bs[BK][BN];

    int tid = threadIdx.x;
    int ty = tid >> 4;
    int tx = tid & 15;
    int rowBase = blockIdx.y * BM;   // i
    int colBase = blockIdx.x * BN;   // j

    float acc[TM][TN];
#pragma unroll
    for (int m = 0; m < TM; m++)
#pragma unroll
        for (int n = 0; n < TN; n++) acc[m][n] = 0.f;

    int aRow = tid >> 5, aCol = (tid & 31) * 4;   // A: 8 rows(k) x 128 cols(i)
    int bRow = tid >> 5, bCol = (tid & 31) * 4;   // B: 8 rows(k) x 128 cols(j)
    const float* Aptr = W + (size_t)aRow * DIM + rowBase + aCol;
    const float* Bptr = Btmp + (size_t)bRow * DIM + colBase + bCol;

    for (int k0 = 0; k0 < DIM; k0 += BK) {
        *(float4*)&As[aRow][aCol] = *(const float4*)(Aptr + (size_t)k0 * DIM);
        *(float4*)&Bs[bRow][bCol] = *(const float4*)(Bptr + (size_t)k0 * DIM);
        __syncthreads();
#pragma unroll
        for (int kk = 0; kk < BK; kk++) {
            float ar[TM], br[TN];
#pragma unroll
            for (int m = 0; m < TM; m++) ar[m] = As[kk][ty * TM + m];
#pragma unroll
            for (int n = 0; n < TN; n++) br[n] = Bs[kk][tx * TN + n];
#pragma unroll
            for (int m = 0; m < TM; m++)
#pragma unroll
                for (int n = 0; n < TN; n++) acc[m][n] += ar[m] * br[n];
        }
        __syncthreads();
    }

#pragma unroll
    for (int m = 0; m < TM; m++) {
        int r = rowBase + ty * TM + m;   // global i
        int c0 = colBase + tx * TN;      // global j start
        // fuse diagonal add
        if (r >= c0 && r < c0 + TN) {
            acc[m][r - c0] += g_diag[b * DIM + r];
        }
        float* cp = C + (size_t)r * DIM + c0;
        *(float4*)cp = make_float4(acc[m][0], acc[m][1], acc[m][2], acc[m][3]);
        *(float4*)(cp + 4) = make_float4(acc[m][4], acc[m][5], acc[m][6], acc[m][7]);
    }
}

// ---------------------------------------------------------------------------
// Launch
// Output layout assumed: [ mu_out (64*1024) | Sigma_out (64*1024*1024) | kl (1) ]
// ---------------------------------------------------------------------------
extern "C" void kernel_launch(void* const* d_in, const int* in_sizes, int n_in,
                              void* d_out, int out_size) {
    const float* mu_in    = (const float*)d_in[0];
    const float* sigma_in = (const float*)d_in[1];
    const float* w_mu     = (const float*)d_in[2];
    const float* w_sigma  = (const float*)d_in[3];
    const float* b_mu     = (const float*)d_in[4];
    const float* b_sigma  = (const float*)d_in[5];
    float* out = (float*)d_out;

    float* out_mu    = out;                                   // 65536
    float* out_sigma = out + (size_t)BATCH * DIM;             // 64*1024*1024
    float* out_kl    = out + (size_t)BATCH * DIM + (size_t)BATCH * DIM * DIM;  // 1

    prep_wsig_kernel<<<DIM, 256>>>(w_sigma);
    prep_dvec_kernel<<<(BATCH * DIM) / 256, 256>>>(sigma_in, mu_in);
    mu_out_kernel<<<dim3(BATCH, DIM / 256), 256>>>(mu_in, w_mu, b_mu, out_mu);
    diag_kernel<<<dim3(BATCH, DIM / 256), 256>>>(b_sigma);
    kl_kernel<<<1, 1024>>>(w_mu, out_kl);
    gemm1_kernel<<<dim3(DIM / BN, DIM / BM, BATCH), 256>>>(sigma_in, w_mu);
    gemm2_kernel<<<dim3(DIM / BN, DIM / BM, BATCH), 256>>>(w_mu, out_sigma);
}

// round 7
// speedup vs baseline: 3.7543x; 3.7497x over previous
#include <cuda_runtime.h>
#include <cuda_bf16.h>
#include <stdint.h>
#include <math.h>

#define BATCH 64
#define DIM 1024
#define KCHUNK 16                      // 1024 / 64 K-elems per chunk
#define STAGE_BYTES 98304              // A_hi 16K | A_lo 16K | B_hi 32K | B_lo 32K
#define SMEM_TOTAL (2 * STAGE_BYTES)   // 196608
#define OFF_AHI 0
#define OFF_ALO 16384
#define OFF_BHI 32768
#define OFF_BLO 65536

// ---------------------------------------------------------------------------
// Device scratch (static — no runtime allocation)
// ---------------------------------------------------------------------------
__device__ __align__(256) __nv_bfloat16 g_sig_hi[67108864];   // sigma split (128MB)
__device__ __align__(256) __nv_bfloat16 g_sig_lo[67108864];
__device__ __align__(256) __nv_bfloat16 g_tmpT_hi[67108864];  // tmpT = (sigma@W)^T split
__device__ __align__(256) __nv_bfloat16 g_tmpT_lo[67108864];
__device__ __align__(256) __nv_bfloat16 g_wT_hi[1048576];     // wT[j][l] = w_mu[l][j]
__device__ __align__(256) __nv_bfloat16 g_wT_lo[1048576];
__device__ __align__(256) float g_wsigT[1048576];   // wsigT[k][i] = softplus(w_sigma[i][k])
__device__ __align__(256) float g_dvec[65536];      // sigma[b][k][k] + mu^2
__device__ __align__(256) float g_diag[65536];      // diag_term[b][i]
__device__ float g_klpart[16];

// ---------------------------------------------------------------------------
// PTX helpers (all plain compute_103-legal: cp.async, ldmatrix, mma.sync)
// ---------------------------------------------------------------------------
__device__ __forceinline__ uint32_t smem_u32(const void* p) {
    return (uint32_t)__cvta_generic_to_shared(p);
}
__device__ __forceinline__ void cp_async16(uint32_t dst, const void* src) {
    asm volatile("cp.async.cg.shared.global [%0], [%1], 16;" :: "r"(dst), "l"(src));
}
__device__ __forceinline__ void cp_commit() {
    asm volatile("cp.async.commit_group;" ::: "memory");
}
template<int N> __device__ __forceinline__ void cp_wait() {
    asm volatile("cp.async.wait_group %0;" :: "n"(N) : "memory");
}
__device__ __forceinline__ void ldsm4(uint32_t* r, uint32_t addr) {
    asm volatile("ldmatrix.sync.aligned.m8n8.x4.shared.b16 {%0,%1,%2,%3}, [%4];"
                 : "=r"(r[0]), "=r"(r[1]), "=r"(r[2]), "=r"(r[3]) : "r"(addr));
}
__device__ __forceinline__ void mma_bf16(float* c, const uint32_t* a, const uint32_t* b) {
    asm volatile(
        "mma.sync.aligned.m16n8k16.row.col.f32.bf16.bf16.f32 "
        "{%0,%1,%2,%3}, {%4,%5,%6,%7}, {%8,%9}, {%0,%1,%2,%3};"
        : "+f"(c[0]), "+f"(c[1]), "+f"(c[2]), "+f"(c[3])
        : "r"(a[0]), "r"(a[1]), "r"(a[2]), "r"(a[3]), "r"(b[0]), "r"(b[1]));
}
__device__ __forceinline__ uint32_t swz(uint32_t x) { return x ^ ((x >> 3) & 0x70); }
__device__ __forceinline__ uint32_t pack_bf2(__nv_bfloat16 a, __nv_bfloat16 b) {
    return (uint32_t)__bfloat16_as_ushort(a) | ((uint32_t)__bfloat16_as_ushort(b) << 16);
}

// ---------------------------------------------------------------------------
// Prep kernels
// ---------------------------------------------------------------------------
__global__ void prep_wsig_kernel(const float* __restrict__ w_sigma) {
    int k = blockIdx.x;
    for (int i = threadIdx.x; i < DIM; i += blockDim.x) {
        float x = w_sigma[i * DIM + k];
        g_wsigT[k * DIM + i] = log1pf(expf(x));
    }
}

__global__ void prep_dvec_kernel(const float* __restrict__ sigma_in,
                                 const float* __restrict__ mu_in) {
    int idx = blockIdx.x * blockDim.x + threadIdx.x;
    if (idx < BATCH * DIM) {
        int b = idx >> 10;
        int k = idx & 1023;
        float m = mu_in[idx];
        g_dvec[idx] = sigma_in[(size_t)b * DIM * DIM + (size_t)k * DIM + k] + m * m;
    }
}

// Transpose + bf16 split of w_mu: wT[j][l] = w_mu[l][j]
__global__ void prep_wT_kernel(const float* __restrict__ w_mu) {
    __shared__ float tile[32][33];
    int bx = blockIdx.x * 32;   // j
    int by = blockIdx.y * 32;   // l
    int tx = threadIdx.x, ty = threadIdx.y;   // block (32, 8)
#pragma unroll
    for (int r = 0; r < 4; r++)
        tile[ty + r * 8][tx] = w_mu[(size_t)(by + ty + r * 8) * DIM + bx + tx];
    __syncthreads();
#pragma unroll
    for (int r = 0; r < 4; r++) {
        float v = tile[tx][ty + r * 8];
        __nv_bfloat16 h = __float2bfloat16(v);
        __nv_bfloat16 l = __float2bfloat16(v - __bfloat162float(h));
        size_t o = (size_t)(bx + ty + r * 8) * DIM + by + tx;
        g_wT_hi[o] = h;
        g_wT_lo[o] = l;
    }
}

// sigma fp32 -> bf16 hi/lo split
__global__ void conv_sigma_kernel(const float* __restrict__ s) {
    size_t i = (size_t)blockIdx.x * 256 + threadIdx.x;
    float4 v = ((const float4*)s)[i];
    __nv_bfloat16 h0 = __float2bfloat16(v.x), h1 = __float2bfloat16(v.y);
    __nv_bfloat16 h2 = __float2bfloat16(v.z), h3 = __float2bfloat16(v.w);
    __nv_bfloat16 l0 = __float2bfloat16(v.x - __bfloat162float(h0));
    __nv_bfloat16 l1 = __float2bfloat16(v.y - __bfloat162float(h1));
    __nv_bfloat16 l2 = __float2bfloat16(v.z - __bfloat162float(h2));
    __nv_bfloat16 l3 = __float2bfloat16(v.w - __bfloat162float(h3));
    ((uint2*)g_sig_hi)[i] = make_uint2(pack_bf2(h0, h1), pack_bf2(h2, h3));
    ((uint2*)g_sig_lo)[i] = make_uint2(pack_bf2(l0, l1), pack_bf2(l2, l3));
}

// mu_out + diag_term fused
__global__ void vec_terms_kernel(const float* __restrict__ mu_in,
                                 const float* __restrict__ w_mu,
                                 const float* __restrict__ b_mu,
                                 const float* __restrict__ b_sigma,
                                 float* __restrict__ out_mu) {
    int b = blockIdx.x;
    int o = blockIdx.y * 256 + threadIdx.x;
    __shared__ float smi[DIM], sdv[DIM];
    for (int t = threadIdx.x; t < DIM; t += 256) {
        smi[t] = mu_in[b * DIM + t];
        sdv[t] = g_dvec[b * DIM + t];
    }
    __syncthreads();
    float am = 0.f, ad = 0.f;
#pragma unroll 8
    for (int k = 0; k < DIM; k++) {
        am += smi[k] * w_mu[k * DIM + o];
        ad += sdv[k] * g_wsigT[k * DIM + o];
    }
    out_mu[b * DIM + o] = am + b_mu[o];
    g_diag[b * DIM + o] = ad + log1pf(expf(b_sigma[o]));
}

__global__ void kl_stage1_kernel(const float* __restrict__ w_mu) {
    int i = blockIdx.x * 64 + threadIdx.x;
    float sq = 0.f, tr = 0.f, det = 1.0f;
    for (int k = 0; k < DIM; k++) {
        float w = w_mu[k * DIM + i];
        sq += w * w;
        float s = g_wsigT[k * DIM + i];
        tr += s;
        det *= s;
    }
    float logdet = (det > 0.f) ? logf(det) : -1000.0f;
    float v = sq + tr - (float)DIM - logdet;
#pragma unroll
    for (int o = 16; o > 0; o >>= 1) v += __shfl_down_sync(0xffffffff, v, o);
    __shared__ float ws[2];
    if ((threadIdx.x & 31) == 0) ws[threadIdx.x >> 5] = v;
    __syncthreads();
    if (threadIdx.x == 0) g_klpart[blockIdx.x] = ws[0] + ws[1];
}

__global__ void kl_stage2_kernel(float* __restrict__ out_kl) {
    float v = (threadIdx.x < 16) ? g_klpart[threadIdx.x] : 0.f;
#pragma unroll
    for (int o = 16; o > 0; o >>= 1) v += __shfl_down_sync(0xffffffff, v, o);
    if (threadIdx.x == 0) *out_kl = 0.5f * v;
}

// ---------------------------------------------------------------------------
// Split-bf16 GEMM via mma.sync (HMMA): D[m][n] = sum_k A[m][k]*B[n][k]
//   A = wT (M tile 128).  B (N tile 256).
//   3 passes into shared fp32 accum: Ahi*Bhi + Alo*Bhi + Ahi*Blo.
// MODE 1: B = sigma split  -> write tmpT hi/lo (bf16)
// MODE 2: B = tmpT split   -> write Sigma_out fp32 (+ diag on m==n)
// 512 threads, 16 warps 4(m) x 4(n), warp tile 32x64.
// ---------------------------------------------------------------------------
template<int MODE>
__global__ void __launch_bounds__(512, 1) gemm_hmma(float* __restrict__ outp) {
    extern __shared__ char sm[];
    const int tid = threadIdx.x, wid = tid >> 5, lane = tid & 31;
    const int b = blockIdx.z;
    const int m0 = blockIdx.y * 128;
    const int n0 = blockIdx.x * 256;
    const uint32_t smem = smem_u32(sm);

    const __nv_bfloat16* __restrict__ Ahi = g_wT_hi;
    const __nv_bfloat16* __restrict__ Alo = g_wT_lo;
    const __nv_bfloat16* __restrict__ Bhi =
        (MODE == 1 ? g_sig_hi : g_tmpT_hi) + (size_t)b * DIM * DIM;
    const __nv_bfloat16* __restrict__ Blo =
        (MODE == 1 ? g_sig_lo : g_tmpT_lo) + (size_t)b * DIM * DIM;

    // ---- load plan: 16B chunks, 128B rows, SW128 swizzle ----
    // A: 128 rows x 8 chunks = 1024 -> 2/thread.  B: 256 rows x 8 = 2048 -> 4/thread.
    uint32_t offA[2], dA[2], offB[4], dB[4];
#pragma unroll
    for (int t = 0; t < 2; t++) {
        int c = t * 512 + tid, row = c >> 3, col = c & 7;
        offA[t] = (uint32_t)(m0 + row) * DIM + col * 8;
        dA[t] = swz(row * 128 + col * 16);
    }
#pragma unroll
    for (int t = 0; t < 4; t++) {
        int c = t * 512 + tid, row = c >> 3, col = c & 7;
        offB[t] = (uint32_t)(n0 + row) * DIM + col * 8;
        dB[t] = swz(row * 128 + col * 16);
    }

    auto load_stage = [&](int kc, int buf) {
        uint32_t sb = smem + buf * STAGE_BYTES;
        uint32_t ko = kc * 64;
#pragma unroll
        for (int t = 0; t < 2; t++) cp_async16(sb + OFF_AHI + dA[t], Ahi + offA[t] + ko);
#pragma unroll
        for (int t = 0; t < 2; t++) cp_async16(sb + OFF_ALO + dA[t], Alo + offA[t] + ko);
#pragma unroll
        for (int t = 0; t < 4; t++) cp_async16(sb + OFF_BHI + dB[t], Bhi + offB[t] + ko);
#pragma unroll
        for (int t = 0; t < 4; t++) cp_async16(sb + OFF_BLO + dB[t], Blo + offB[t] + ko);
        cp_commit();
    };

    // ---- per-thread fragment geometry ----
    const int wm = wid >> 2;            // 0..3 -> m warp base = wm*32
    const int wn = wid & 3;             // 0..3 -> n warp base = wn*64
    const int g = lane >> 3, r = lane & 7;
    // A ldmatrix x4: tiles (m,k0)(m+8,k0)(m,k0+8)(m+8,k0+8)
    const int rowA_off = (g & 1) * 8 + r;             // + mt*16 + wm*32
    const int kA_off = (g >> 1) * 8;                  // bf16 elems
    // B ldmatrix x4: tiles (n,k0)(n,k0+8)(n+8,k0)(n+8,k0+8)
    const int rowB_off = (g >> 1) * 8 + r;            // + pair*16 + wn*64
    const int kB_off = (g & 1) * 8;

    float acc[2][8][4];
#pragma unroll
    for (int mt = 0; mt < 2; mt++)
#pragma unroll
        for (int nt = 0; nt < 8; nt++)
#pragma unroll
            for (int q = 0; q < 4; q++) acc[mt][nt][q] = 0.f;

    load_stage(0, 0);

    for (int kc = 0; kc < KCHUNK; kc++) {
        int buf = kc & 1;
        if (kc + 1 < KCHUNK) {
            load_stage(kc + 1, buf ^ 1);
            cp_wait<1>();
        } else {
            cp_wait<0>();
        }
        __syncthreads();
        uint32_t sb = smem + buf * STAGE_BYTES;

#pragma unroll
        for (int ks = 0; ks < 4; ks++) {
            uint32_t ahi[2][4], alo[2][4], bb[8][2];
            int kbyte = (ks * 16 + kA_off) * 2;
#pragma unroll
            for (int mt = 0; mt < 2; mt++) {
                int rowA = wm * 32 + mt * 16 + rowA_off;
                ldsm4(ahi[mt], sb + OFF_AHI + swz(rowA * 128 + kbyte));
                ldsm4(alo[mt], sb + OFF_ALO + swz(rowA * 128 + kbyte));
            }
            int kbyteB = (ks * 16 + kB_off) * 2;
            // B_hi -> HH + LH passes
#pragma unroll
            for (int p = 0; p < 4; p++) {
                int rowB = wn * 64 + p * 16 + rowB_off;
                ldsm4(&bb[p * 2][0], sb + OFF_BHI + swz(rowB * 128 + kbyteB));
            }
#pragma unroll
            for (int mt = 0; mt < 2; mt++)
#pragma unroll
                for (int nt = 0; nt < 8; nt++) {
                    mma_bf16(acc[mt][nt], ahi[mt], bb[nt]);
                    mma_bf16(acc[mt][nt], alo[mt], bb[nt]);
                }
            // B_lo -> HL pass (reuse bb regs)
#pragma unroll
            for (int p = 0; p < 4; p++) {
                int rowB = wn * 64 + p * 16 + rowB_off;
                ldsm4(&bb[p * 2][0], sb + OFF_BLO + swz(rowB * 128 + kbyteB));
            }
#pragma unroll
            for (int mt = 0; mt < 2; mt++)
#pragma unroll
                for (int nt = 0; nt < 8; nt++)
                    mma_bf16(acc[mt][nt], ahi[mt], bb[nt]);
        }
        __syncthreads();
    }

    // ---- epilogue ----
    const int t4 = lane >> 2, t2 = (lane & 3) * 2;
#pragma unroll
    for (int mt = 0; mt < 2; mt++) {
#pragma unroll
        for (int nt = 0; nt < 8; nt++) {
            int mA = m0 + wm * 32 + mt * 16 + t4;
            int mB = mA + 8;
            int n = n0 + wn * 64 + nt * 8 + t2;
            float* c = acc[mt][nt];
            if (MODE == 1) {
                __nv_bfloat16 h0 = __float2bfloat16(c[0]);
                __nv_bfloat16 h1 = __float2bfloat16(c[1]);
                __nv_bfloat16 h2 = __float2bfloat16(c[2]);
                __nv_bfloat16 h3 = __float2bfloat16(c[3]);
                __nv_bfloat16 l0 = __float2bfloat16(c[0] - __bfloat162float(h0));
                __nv_bfloat16 l1 = __float2bfloat16(c[1] - __bfloat162float(h1));
                __nv_bfloat16 l2 = __float2bfloat16(c[2] - __bfloat162float(h2));
                __nv_bfloat16 l3 = __float2bfloat16(c[3] - __bfloat162float(h3));
                size_t base = (size_t)b * DIM * DIM;
                *(uint32_t*)(g_tmpT_hi + base + (size_t)mA * DIM + n) = pack_bf2(h0, h1);
                *(uint32_t*)(g_tmpT_lo + base + (size_t)mA * DIM + n) = pack_bf2(l0, l1);
                *(uint32_t*)(g_tmpT_hi + base + (size_t)mB * DIM + n) = pack_bf2(h2, h3);
                *(uint32_t*)(g_tmpT_lo + base + (size_t)mB * DIM + n) = pack_bf2(l2, l3);
            } else {
                if (n == mA)     c[0] += g_diag[b * DIM + mA];
                if (n + 1 == mA) c[1] += g_diag[b * DIM + mA];
                if (n == mB)     c[2] += g_diag[b * DIM + mB];
                if (n + 1 == mB) c[3] += g_diag[b * DIM + mB];
                float* o = outp + (size_t)b * DIM * DIM;
                *(float2*)(o + (size_t)mA * DIM + n) = make_float2(c[0], c[1]);
                *(float2*)(o + (size_t)mB * DIM + n) = make_float2(c[2], c[3]);
            }
        }
    }
}

// ---------------------------------------------------------------------------
// Launch.  Output layout: [ mu_out (64*1024) | Sigma_out (64*1024*1024) | kl ]
// ---------------------------------------------------------------------------
extern "C" void kernel_launch(void* const* d_in, const int* in_sizes, int n_in,
                              void* d_out, int out_size) {
    const float* mu_in    = (const float*)d_in[0];
    const float* sigma_in = (const float*)d_in[1];
    const float* w_mu     = (const float*)d_in[2];
    const float* w_sigma  = (const float*)d_in[3];
    const float* b_mu     = (const float*)d_in[4];
    const float* b_sigma  = (const float*)d_in[5];
    float* out = (float*)d_out;

    float* out_mu    = out;
    float* out_sigma = out + (size_t)BATCH * DIM;
    float* out_kl    = out + (size_t)BATCH * DIM + (size_t)BATCH * DIM * DIM;

    cudaFuncSetAttribute(gemm_hmma<1>, cudaFuncAttributeMaxDynamicSharedMemorySize, SMEM_TOTAL);
    cudaFuncSetAttribute(gemm_hmma<2>, cudaFuncAttributeMaxDynamicSharedMemorySize, SMEM_TOTAL);

    prep_wsig_kernel<<<DIM, 256>>>(w_sigma);
    prep_dvec_kernel<<<(BATCH * DIM) / 256, 256>>>(sigma_in, mu_in);
    prep_wT_kernel<<<dim3(32, 32), dim3(32, 8)>>>(w_mu);
    conv_sigma_kernel<<<65536, 256>>>(sigma_in);
    vec_terms_kernel<<<dim3(BATCH, DIM / 256), 256>>>(mu_in, w_mu, b_mu, b_sigma, out_mu);
    kl_stage1_kernel<<<16, 64>>>(w_mu);
    kl_stage2_kernel<<<1, 32>>>(out_kl);
    gemm_hmma<1><<<dim3(4, 8, BATCH), 512, SMEM_TOTAL>>>(nullptr);
    gemm_hmma<2><<<dim3(4, 8, BATCH), 512, SMEM_TOTAL>>>(out_sigma);
}

// round 8
// speedup vs baseline: 7.3788x; 1.9654x over previous
#include <cuda_runtime.h>
#include <cuda_bf16.h>
#include <stdint.h>
#include <math.h>

#define BATCH 64
#define DIM 1024
#define KCHUNK 16                      // 1024 / 64 K-elems per chunk
#define STAGE_BYTES 49152              // A 16K | B 32K
#define SMEM_TOTAL (2 * STAGE_BYTES)   // 98304
#define OFF_A 0
#define OFF_B 16384

// ---------------------------------------------------------------------------
// Device scratch (static — no runtime allocation)
// ---------------------------------------------------------------------------
__device__ __align__(256) __nv_bfloat16 g_sig[67108864];    // sigma bf16 (128MB)
__device__ __align__(256) __nv_bfloat16 g_tmpT[67108864];   // tmpT = (sigma@W)^T bf16
__device__ __align__(256) __nv_bfloat16 g_wT[1048576];      // wT[j][l] = w_mu[l][j]
__device__ __align__(256) float g_wsigT[1048576];   // wsigT[k][i] = softplus(w_sigma[i][k])
__device__ __align__(256) float g_dvec[65536];      // sigma[b][k][k] + mu^2
__device__ __align__(256) float g_diag[65536];      // diag_term[b][i]
__device__ float g_klpart[16];

// ---------------------------------------------------------------------------
// PTX helpers (plain compute_103-legal: cp.async, ldmatrix, mma.sync)
// ---------------------------------------------------------------------------
__device__ __forceinline__ uint32_t smem_u32(const void* p) {
    return (uint32_t)__cvta_generic_to_shared(p);
}
__device__ __forceinline__ void cp_async16(uint32_t dst, const void* src) {
    asm volatile("cp.async.cg.shared.global [%0], [%1], 16;" :: "r"(dst), "l"(src));
}
__device__ __forceinline__ void cp_commit() {
    asm volatile("cp.async.commit_group;" ::: "memory");
}
template<int N> __device__ __forceinline__ void cp_wait() {
    asm volatile("cp.async.wait_group %0;" :: "n"(N) : "memory");
}
__device__ __forceinline__ void ldsm4(uint32_t* r, uint32_t addr) {
    asm volatile("ldmatrix.sync.aligned.m8n8.x4.shared.b16 {%0,%1,%2,%3}, [%4];"
                 : "=r"(r[0]), "=r"(r[1]), "=r"(r[2]), "=r"(r[3]) : "r"(addr));
}
__device__ __forceinline__ void mma_bf16(float* c, const uint32_t* a, const uint32_t* b) {
    asm volatile(
        "mma.sync.aligned.m16n8k16.row.col.f32.bf16.bf16.f32 "
        "{%0,%1,%2,%3}, {%4,%5,%6,%7}, {%8,%9}, {%0,%1,%2,%3};"
        : "+f"(c[0]), "+f"(c[1]), "+f"(c[2]), "+f"(c[3])
        : "r"(a[0]), "r"(a[1]), "r"(a[2]), "r"(a[3]), "r"(b[0]), "r"(b[1]));
}
__device__ __forceinline__ uint32_t swz(uint32_t x) { return x ^ ((x >> 3) & 0x70); }
__device__ __forceinline__ uint32_t pack_bf2(__nv_bfloat16 a, __nv_bfloat16 b) {
    return (uint32_t)__bfloat16_as_ushort(a) | ((uint32_t)__bfloat16_as_ushort(b) << 16);
}

// ---------------------------------------------------------------------------
// Prep kernels
// ---------------------------------------------------------------------------
__global__ void prep_wsig_kernel(const float* __restrict__ w_sigma) {
    int k = blockIdx.x;
    for (int i = threadIdx.x; i < DIM; i += blockDim.x) {
        float x = w_sigma[i * DIM + k];
        g_wsigT[k * DIM + i] = log1pf(expf(x));
    }
}

__global__ void prep_dvec_kernel(const float* __restrict__ sigma_in,
                                 const float* __restrict__ mu_in) {
    int idx = blockIdx.x * blockDim.x + threadIdx.x;
    if (idx < BATCH * DIM) {
        int b = idx >> 10;
        int k = idx & 1023;
        float m = mu_in[idx];
        g_dvec[idx] = sigma_in[(size_t)b * DIM * DIM + (size_t)k * DIM + k] + m * m;
    }
}

// Transpose + bf16 of w_mu: wT[j][l] = w_mu[l][j]
__global__ void prep_wT_kernel(const float* __restrict__ w_mu) {
    __shared__ float tile[32][33];
    int bx = blockIdx.x * 32;   // j
    int by = blockIdx.y * 32;   // l
    int tx = threadIdx.x, ty = threadIdx.y;   // block (32, 8)
#pragma unroll
    for (int r = 0; r < 4; r++)
        tile[ty + r * 8][tx] = w_mu[(size_t)(by + ty + r * 8) * DIM + bx + tx];
    __syncthreads();
#pragma unroll
    for (int r = 0; r < 4; r++) {
        float v = tile[tx][ty + r * 8];
        g_wT[(size_t)(bx + ty + r * 8) * DIM + by + tx] = __float2bfloat16(v);
    }
}

// sigma fp32 -> bf16
__global__ void conv_sigma_kernel(const float* __restrict__ s) {
    size_t i = (size_t)blockIdx.x * 256 + threadIdx.x;
    float4 v = ((const float4*)s)[i];
    ((uint2*)g_sig)[i] = make_uint2(
        pack_bf2(__float2bfloat16(v.x), __float2bfloat16(v.y)),
        pack_bf2(__float2bfloat16(v.z), __float2bfloat16(v.w)));
}

// mu_out + diag_term fused (exact fp32 — these dominate the error metric)
__global__ void vec_terms_kernel(const float* __restrict__ mu_in,
                                 const float* __restrict__ w_mu,
                                 const float* __restrict__ b_mu,
                                 const float* __restrict__ b_sigma,
                                 float* __restrict__ out_mu) {
    int b = blockIdx.x;
    int o = blockIdx.y * 256 + threadIdx.x;
    __shared__ float smi[DIM], sdv[DIM];
    for (int t = threadIdx.x; t < DIM; t += 256) {
        smi[t] = mu_in[b * DIM + t];
        sdv[t] = g_dvec[b * DIM + t];
    }
    __syncthreads();
    float am = 0.f, ad = 0.f;
#pragma unroll 8
    for (int k = 0; k < DIM; k++) {
        am += smi[k] * w_mu[k * DIM + o];
        ad += sdv[k] * g_wsigT[k * DIM + o];
    }
    out_mu[b * DIM + o] = am + b_mu[o];
    g_diag[b * DIM + o] = ad + log1pf(expf(b_sigma[o]));
}

__global__ void kl_stage1_kernel(const float* __restrict__ w_mu) {
    int i = blockIdx.x * 64 + threadIdx.x;
    float sq = 0.f, tr = 0.f, det = 1.0f;
    for (int k = 0; k < DIM; k++) {
        float w = w_mu[k * DIM + i];
        sq += w * w;
        float s = g_wsigT[k * DIM + i];
        tr += s;
        det *= s;
    }
    float logdet = (det > 0.f) ? logf(det) : -1000.0f;
    float v = sq + tr - (float)DIM - logdet;
#pragma unroll
    for (int o = 16; o > 0; o >>= 1) v += __shfl_down_sync(0xffffffff, v, o);
    __shared__ float ws[2];
    if ((threadIdx.x & 31) == 0) ws[threadIdx.x >> 5] = v;
    __syncthreads();
    if (threadIdx.x == 0) g_klpart[blockIdx.x] = ws[0] + ws[1];
}

__global__ void kl_stage2_kernel(float* __restrict__ out_kl) {
    float v = (threadIdx.x < 16) ? g_klpart[threadIdx.x] : 0.f;
#pragma unroll
    for (int o = 16; o > 0; o >>= 1) v += __shfl_down_sync(0xffffffff, v, o);
    if (threadIdx.x == 0) *out_kl = 0.5f * v;
}

// ---------------------------------------------------------------------------
// bf16 GEMM via mma.sync (HMMA): D[m][n] = sum_k A[m][k]*B[n][k]
//   A = wT (M tile 128).  B (N tile 256).  Single pass, fp32 accum.
// MODE 1: B = g_sig  -> write tmpT bf16
// MODE 2: B = g_tmpT -> write Sigma_out fp32 (+ diag on m==n)
// 512 threads, 16 warps 4(m) x 4(n), warp tile 32x64.
// ---------------------------------------------------------------------------
template<int MODE>
__global__ void __launch_bounds__(512, 1) gemm_hmma(float* __restrict__ outp) {
    extern __shared__ char sm[];
    const int tid = threadIdx.x, wid = tid >> 5, lane = tid & 31;
    const int b = blockIdx.z;
    const int m0 = blockIdx.y * 128;
    const int n0 = blockIdx.x * 256;
    const uint32_t smem = smem_u32(sm);

    const __nv_bfloat16* __restrict__ A = g_wT;
    const __nv_bfloat16* __restrict__ B =
        (MODE == 1 ? g_sig : g_tmpT) + (size_t)b * DIM * DIM;

    // ---- load plan: 16B chunks, 128B rows, SW128 swizzle ----
    // A: 128 rows x 8 chunks = 1024 -> 2/thread.  B: 256 rows x 8 = 2048 -> 4/thread.
    uint32_t offA[2], dA[2], offB[4], dB[4];
#pragma unroll
    for (int t = 0; t < 2; t++) {
        int c = t * 512 + tid, row = c >> 3, col = c & 7;
        offA[t] = (uint32_t)(m0 + row) * DIM + col * 8;
        dA[t] = swz(row * 128 + col * 16);
    }
#pragma unroll
    for (int t = 0; t < 4; t++) {
        int c = t * 512 + tid, row = c >> 3, col = c & 7;
        offB[t] = (uint32_t)(n0 + row) * DIM + col * 8;
        dB[t] = swz(row * 128 + col * 16);
    }

    auto load_stage = [&](int kc, int buf) {
        uint32_t sb = smem + buf * STAGE_BYTES;
        uint32_t ko = kc * 64;
#pragma unroll
        for (int t = 0; t < 2; t++) cp_async16(sb + OFF_A + dA[t], A + offA[t] + ko);
#pragma unroll
        for (int t = 0; t < 4; t++) cp_async16(sb + OFF_B + dB[t], B + offB[t] + ko);
        cp_commit();
    };

    // ---- per-thread fragment geometry ----
    const int wm = wid >> 2;            // m warp base = wm*32
    const int wn = wid & 3;             // n warp base = wn*64
    const int g = lane >> 3, r = lane & 7;
    const int rowA_off = (g & 1) * 8 + r;
    const int kA_off = (g >> 1) * 8;
    const int rowB_off = (g >> 1) * 8 + r;
    const int kB_off = (g & 1) * 8;

    float acc[2][8][4];
#pragma unroll
    for (int mt = 0; mt < 2; mt++)
#pragma unroll
        for (int nt = 0; nt < 8; nt++)
#pragma unroll
            for (int q = 0; q < 4; q++) acc[mt][nt][q] = 0.f;

    load_stage(0, 0);

    for (int kc = 0; kc < KCHUNK; kc++) {
        int buf = kc & 1;
        if (kc + 1 < KCHUNK) {
            load_stage(kc + 1, buf ^ 1);
            cp_wait<1>();
        } else {
            cp_wait<0>();
        }
        __syncthreads();
        uint32_t sb = smem + buf * STAGE_BYTES;

#pragma unroll
        for (int ks = 0; ks < 4; ks++) {
            uint32_t aa[2][4], bb[8][2];
            int kbyte = (ks * 16 + kA_off) * 2;
#pragma unroll
            for (int mt = 0; mt < 2; mt++) {
                int rowA = wm * 32 + mt * 16 + rowA_off;
                ldsm4(aa[mt], sb + OFF_A + swz(rowA * 128 + kbyte));
            }
            int kbyteB = (ks * 16 + kB_off) * 2;
#pragma unroll
            for (int p = 0; p < 4; p++) {
                int rowB = wn * 64 + p * 16 + rowB_off;
                ldsm4(&bb[p * 2][0], sb + OFF_B + swz(rowB * 128 + kbyteB));
            }
#pragma unroll
            for (int mt = 0; mt < 2; mt++)
#pragma unroll
                for (int nt = 0; nt < 8; nt++)
                    mma_bf16(acc[mt][nt], aa[mt], bb[nt]);
        }
        __syncthreads();
    }

    // ---- epilogue ----
    const int t4 = lane >> 2, t2 = (lane & 3) * 2;
#pragma unroll
    for (int mt = 0; mt < 2; mt++) {
#pragma unroll
        for (int nt = 0; nt < 8; nt++) {
            int mA = m0 + wm * 32 + mt * 16 + t4;
            int mB = mA + 8;
            int n = n0 + wn * 64 + nt * 8 + t2;
            float* c = acc[mt][nt];
            if (MODE == 1) {
                size_t base = (size_t)b * DIM * DIM;
                *(uint32_t*)(g_tmpT + base + (size_t)mA * DIM + n) =
                    pack_bf2(__float2bfloat16(c[0]), __float2bfloat16(c[1]));
                *(uint32_t*)(g_tmpT + base + (size_t)mB * DIM + n) =
                    pack_bf2(__float2bfloat16(c[2]), __float2bfloat16(c[3]));
            } else {
                if (n == mA)     c[0] += g_diag[b * DIM + mA];
                if (n + 1 == mA) c[1] += g_diag[b * DIM + mA];
                if (n == mB)     c[2] += g_diag[b * DIM + mB];
                if (n + 1 == mB) c[3] += g_diag[b * DIM + mB];
                float* o = outp + (size_t)b * DIM * DIM;
                *(float2*)(o + (size_t)mA * DIM + n) = make_float2(c[0], c[1]);
                *(float2*)(o + (size_t)mB * DIM + n) = make_float2(c[2], c[3]);
            }
        }
    }
}

// ---------------------------------------------------------------------------
// Launch.  Output layout: [ mu_out (64*1024) | Sigma_out (64*1024*1024) | kl ]
// ---------------------------------------------------------------------------
extern "C" void kernel_launch(void* const* d_in, const int* in_sizes, int n_in,
                              void* d_out, int out_size) {
    const float* mu_in    = (const float*)d_in[0];
    const float* sigma_in = (const float*)d_in[1];
    const float* w_mu     = (const float*)d_in[2];
    const float* w_sigma  = (const float*)d_in[3];
    const float* b_mu     = (const float*)d_in[4];
    const float* b_sigma  = (const float*)d_in[5];
    float* out = (float*)d_out;

    float* out_mu    = out;
    float* out_sigma = out + (size_t)BATCH * DIM;
    float* out_kl    = out + (size_t)BATCH * DIM + (size_t)BATCH * DIM * DIM;

    cudaFuncSetAttribute(gemm_hmma<1>, cudaFuncAttributeMaxDynamicSharedMemorySize, SMEM_TOTAL);
    cudaFuncSetAttribute(gemm_hmma<2>, cudaFuncAttributeMaxDynamicSharedMemorySize, SMEM_TOTAL);

    prep_wsig_kernel<<<DIM, 256>>>(w_sigma);
    prep_dvec_kernel<<<(BATCH * DIM) / 256, 256>>>(sigma_in, mu_in);
    prep_wT_kernel<<<dim3(32, 32), dim3(32, 8)>>>(w_mu);
    conv_sigma_kernel<<<65536, 256>>>(sigma_in);
    vec_terms_kernel<<<dim3(BATCH, DIM / 256), 256>>>(mu_in, w_mu, b_mu, b_sigma, out_mu);
    kl_stage1_kernel<<<16, 64>>>(w_mu);
    kl_stage2_kernel<<<1, 32>>>(out_kl);
    gemm_hmma<1><<<dim3(4, 8, BATCH), 512, SMEM_TOTAL>>>(nullptr);
    gemm_hmma<2><<<dim3(4, 8, BATCH), 512, SMEM_TOTAL>>>(out_sigma);
}